// round 11
// baseline (speedup 1.0000x reference)
#include <cuda_runtime.h>

#define NB      8
#define NHEADS  12
#define HH      24
#define SEQ     576
#define DIM     64
#define NPOS    24
#define BATCH   96
#define KPAD    28          // B row stride (words): 16B-aligned, tx*28 mod 32 distinct
#define ATPAD   68          // AT row stride (words): 272 B, 16B-aligned at every k

// Scratch: pe_x_flat / pe_y_flat  [BATCH][SEQ][NPOS]
__device__ __align__(16) float g_Vx[BATCH * SEQ * NPOS];
__device__ __align__(16) float g_Vy[BATCH * SEQ * NPOS];

__device__ __forceinline__ float sigmoidf_(float x) {
    return 1.0f / (1.0f + __expf(-x));
}

__device__ __forceinline__ unsigned long long fma2(unsigned long long a,
                                                   unsigned long long b,
                                                   unsigned long long c) {
    unsigned long long d;
    asm("fma.rn.f32x2 %0, %1, %2, %3;" : "=l"(d) : "l"(a), "l"(b), "l"(c));
    return d;
}

__device__ __forceinline__ unsigned long long pack2(float lo, float hi) {
    unsigned long long r;
    asm("mov.b64 %0, {%1, %2};" : "=l"(r) : "f"(lo), "f"(hi));
    return r;
}

__device__ __forceinline__ float fsqrt_approx(float x) {
    float r;
    asm("sqrt.approx.f32 %0, %1;" : "=f"(r) : "f"(x));
    return r;
}

// ---------------------------------------------------------------------------
// Kernel 1: fused CoPE, both paths in one block (512 threads, path = t>>8).
// EXACT R6 form — measured 51-53 us.
// ---------------------------------------------------------------------------
__global__ void __launch_bounds__(512) cope_kernel(
    const float* __restrict__ query,      // [8,12,576,64]
    const float* __restrict__ attn,       // [8,12,576,576]
    const float* __restrict__ pex,        // [64,24]
    const float* __restrict__ pey)        // [64,24]
{
    __shared__ __align__(16) float q_s[2][HH * 68];
    __shared__ __align__(16) float pe_s[2][DIM * NPOS];
    __shared__ __align__(8)  float li[2][HH * 26];

    int t    = threadIdx.x;
    int path = t >> 8;
    int tp   = t & 255;

    int id   = blockIdx.x;
    int n    = id / 12;
    int m    = id % 12;
    int b_a  = id / 288;
    int hd_a = (id / 24) % 12;
    int r_a  = id % 24;
    int b_q  = n / 24;
    int s_q  = n % 24;

    {
        const float4* pe4 = (const float4*)(path ? pey : pex);
        float4* d4 = (float4*)pe_s[path];
        for (int idx = tp; idx < DIM * NPOS / 4; idx += 256)
            d4[idx] = pe4[idx];
    }

    if (!path) {
        const float4* qb = (const float4*)(query + (((size_t)(b_q * 12 + m)) * SEQ + s_q * 24) * DIM);
        for (int idx = tp; idx < HH * DIM / 4; idx += 256) {
            int rr = idx >> 4, c4 = (idx & 15) * 4;
            *(float4*)&q_s[0][rr * 68 + c4] = qb[idx];
        }
    } else {
        const float* qb = query + (((size_t)(b_q * 12 + m)) * SEQ + s_q) * DIM;
        for (int idx = tp; idx < HH * DIM / 4; idx += 256) {
            int rr = idx >> 4, c4 = (idx & 15) * 4;
            *(float4*)&q_s[1][rr * 68 + c4] = *(const float4*)(qb + (size_t)rr * (24 * DIM) + c4);
        }
    }
    __syncthreads();

    for (int o = tp; o < HH * 12; o += 256) {
        int j  = o / 12;
        int pp = o - j * 12;
        const float4* qr4 = (const float4*)&q_s[path][j * 68];
        const float*  pr  = pe_s[path] + 2 * pp;
        unsigned long long acc = 0ull;
        #pragma unroll
        for (int dq = 0; dq < 16; dq++) {
            float4 q4 = qr4[dq];
            float2 v0 = *(const float2*)(pr + (4 * dq + 0) * NPOS);
            float2 v1 = *(const float2*)(pr + (4 * dq + 1) * NPOS);
            float2 v2 = *(const float2*)(pr + (4 * dq + 2) * NPOS);
            float2 v3 = *(const float2*)(pr + (4 * dq + 3) * NPOS);
            acc = fma2(pack2(q4.x, q4.x), pack2(v0.x, v0.y), acc);
            acc = fma2(pack2(q4.y, q4.y), pack2(v1.x, v1.y), acc);
            acc = fma2(pack2(q4.z, q4.z), pack2(v2.x, v2.y), acc);
            acc = fma2(pack2(q4.w, q4.w), pack2(v3.x, v3.y), acc);
        }
        *(float2*)(&li[path][j * 26 + 2 * pp]) = *(float2*)&acc;
    }
    __syncthreads();

    int w    = (t >> 5) & 7;
    int lane = t & 31;
    int bh   = b_q * 12 + m;
    for (int j = w; j < HH; j += 8) {
        const float* arow;
        int astride;
        float* dst;
        if (!path) {
            arow = attn + (((size_t)(b_a * 12 + hd_a)) * SEQ + (size_t)(r_a * 24 + j)) * SEQ
                        + (size_t)(r_a * 24);
            astride = 1;
            dst = g_Vx + ((size_t)bh * SEQ + (size_t)(s_q * 24 + j)) * NPOS;
        } else {
            arow = attn + (((size_t)(b_a * 12 + hd_a)) * SEQ + (size_t)(j * 24 + r_a)) * SEQ
                        + (size_t)r_a;
            astride = 24;
            dst = g_Vy + ((size_t)bh * SEQ + (size_t)(j * 24 + s_q)) * NPOS;
        }
        float v = 0.0f;
        if (lane < NPOS)
            v = sigmoidf_(arow[lane * astride]);
        #pragma unroll
        for (int d = 1; d < 32; d <<= 1) {
            float tv = __shfl_down_sync(0xffffffffu, v, d);
            if (lane + d < NPOS) v += tv;
        }
        if (lane < NPOS) {
            float pp = fminf(v, (float)(NPOS - 1));
            float pf = floorf(pp);
            int   ifl = (int)pf;
            int   ic  = (int)ceilf(pp);
            float wq  = pp - pf;
            float val = li[path][j * 26 + ic] * wq + li[path][j * 26 + ifl] * (1.0f - wq);
            dst[lane] = val;
        }
    }
}

// ---------------------------------------------------------------------------
// Kernel 2: fused double-cdist + mix. R8 structure, reg-slimmed mainloop,
// __launch_bounds__(128, 5): a-operands hoisted per k2 (16 regs), b-side in
// two half-passes of bv[4] (8 regs live) -> peak live ~95 regs, cap 102.
// ---------------------------------------------------------------------------
union DistSm {
    struct { float AT[2][NPOS * ATPAD]; float B[2][64 * KPAD]; } m;
    float T[64 * 65];
};

__global__ void __launch_bounds__(128, 5) dist_kernel(
    const float* __restrict__ wxp,
    float* __restrict__ out)
{
    __shared__ __align__(16) DistSm sm;
    __shared__ float nA[2][64];
    __shared__ float nB[2][64];

    int bz = blockIdx.y;
    int u = blockIdx.x;
    int ti = 0;
    #pragma unroll 1
    while (u >= (9 - ti)) { u -= (9 - ti); ti++; }
    int tj = ti + u;
    int p0 = ti * 64;
    int q0 = tj * 64;

    int t  = threadIdx.x;     // 0..127
    int sg = t >> 6;          // s-path group
    int lt = t & 63;
    int tx = lt & 7;
    int ty = lt >> 3;

    #pragma unroll
    for (int s = 0; s < 2; s++) {
        const float* V = s ? g_Vy : g_Vx;
        const float4* ga = (const float4*)(V + ((size_t)bz * SEQ + p0) * NPOS);
        const float4* gb = (const float4*)(V + ((size_t)bz * SEQ + q0) * NPOS);
        for (int idx = t; idx < 64 * NPOS / 4; idx += 128) {   // 384 float4
            int r = idx / 6, c = (idx - r * 6) * 4;
            float4 va = ga[idx];
            sm.m.AT[s][(c + 0) * ATPAD + r] = va.x;
            sm.m.AT[s][(c + 1) * ATPAD + r] = va.y;
            sm.m.AT[s][(c + 2) * ATPAD + r] = va.z;
            sm.m.AT[s][(c + 3) * ATPAD + r] = va.w;
            *(float4*)&sm.m.B[s][r * KPAD + c] = gb[idx];
        }
    }
    __syncthreads();

    for (int o = t; o < 256; o += 128) {
        int s  = (o >> 7) & 1;
        int ab = (o >> 6) & 1;
        int r  = o & 63;
        float acc = 0.0f;
        if (ab) {
            const float* src = &sm.m.B[s][r * KPAD];
            #pragma unroll
            for (int k = 0; k < NPOS; k++)
                acc = fmaf(src[k], src[k], acc);
            nB[s][r] = acc;
        } else {
            const float* src = &sm.m.AT[s][r];
            #pragma unroll
            for (int k = 0; k < NPOS; k++) {
                float v = src[k * ATPAD];
                acc = fmaf(v, v, acc);
            }
            nA[s][r] = acc;
        }
    }
    __syncthreads();

    float wxv = *wxp;

    const float* ATs = sm.m.AT[sg];
    const float* Bs  = sm.m.B[sg];
    unsigned long long acc[2][2][8];   // [h][d][j]: rows 4ty+32h+2d(,+1), col tx+8j
    #pragma unroll
    for (int h = 0; h < 2; h++)
        #pragma unroll
        for (int d = 0; d < 2; d++)
            #pragma unroll
            for (int j = 0; j < 8; j++) acc[h][d][j] = 0ull;

    #pragma unroll
    for (int k2 = 0; k2 < NPOS / 2; k2++) {
        // Hoist a-operands for both k of this pair: 4 LDS.128 -> 16 regs
        unsigned long long a2[2][2][2];   // [kk][h][half]
        #pragma unroll
        for (int kk = 0; kk < 2; kk++)
            #pragma unroll
            for (int h = 0; h < 2; h++) {
                float4 av = *(const float4*)(ATs + (2 * k2 + kk) * ATPAD + 4 * ty + 32 * h);
                a2[kk][h][0] = pack2(av.x, av.y);
                a2[kk][h][1] = pack2(av.z, av.w);
            }
        // b-side in two half-passes to bound live registers
        #pragma unroll
        for (int jh = 0; jh < 2; jh++) {
            float2 bv[4];
            #pragma unroll
            for (int jj = 0; jj < 4; jj++)
                bv[jj] = *(const float2*)(Bs + (tx + 8 * (4 * jh + jj)) * KPAD + 2 * k2);
            #pragma unroll
            for (int kk = 0; kk < 2; kk++)
                #pragma unroll
                for (int jj = 0; jj < 4; jj++) {
                    int j = 4 * jh + jj;
                    float bk = kk ? bv[jj].y : bv[jj].x;
                    unsigned long long b2 = pack2(bk, bk);
                    #pragma unroll
                    for (int h = 0; h < 2; h++) {
                        acc[h][0][j] = fma2(a2[kk][h][0], b2, acc[h][0][j]);
                        acc[h][1][j] = fma2(a2[kk][h][1], b2, acc[h][1][j]);
                    }
                }
        }
    }
    __syncthreads();   // all reads of AT/B done before T overlays them

    if (sg == 1) {
        float scale = 1.0f - wxv;
        #pragma unroll
        for (int h = 0; h < 2; h++)
            #pragma unroll
            for (int d = 0; d < 2; d++) {
                int r = 4 * ty + 32 * h + 2 * d;
                float na0 = nA[1][r], na1 = nA[1][r + 1];
                #pragma unroll
                for (int j = 0; j < 8; j++) {
                    int c = tx + 8 * j;
                    float nb = nB[1][c];
                    float2 g = *(float2*)&acc[h][d][j];
                    float d20 = fmaxf(fmaf(-2.0f, g.x, na0 + nb), 0.0f);
                    float d21 = fmaxf(fmaf(-2.0f, g.y, na1 + nb), 0.0f);
                    sm.T[r * 65 + c]       = scale * fsqrt_approx(d20);
                    sm.T[(r + 1) * 65 + c] = scale * fsqrt_approx(d21);
                }
            }
    }
    __syncthreads();

    if (sg == 0) {
        float scale = wxv;
        #pragma unroll
        for (int h = 0; h < 2; h++)
            #pragma unroll
            for (int d = 0; d < 2; d++) {
                int r = 4 * ty + 32 * h + 2 * d;
                float na0 = nA[0][r], na1 = nA[0][r + 1];
                #pragma unroll
                for (int j = 0; j < 8; j++) {
                    int c = tx + 8 * j;
                    float nb = nB[0][c];
                    float2 g = *(float2*)&acc[h][d][j];
                    float d20 = fmaxf(fmaf(-2.0f, g.x, na0 + nb), 0.0f);
                    float d21 = fmaxf(fmaf(-2.0f, g.y, na1 + nb), 0.0f);
                    float f0 = fmaf(scale, fsqrt_approx(d20), sm.T[r * 65 + c]);
                    float f1 = fmaf(scale, fsqrt_approx(d21), sm.T[(r + 1) * 65 + c]);
                    if (p0 + r == q0 + c)     f0 = 0.0f;
                    if (p0 + r + 1 == q0 + c) f1 = 0.0f;
                    sm.T[r * 65 + c]       = f0;
                    sm.T[(r + 1) * 65 + c] = f1;
                }
            }
    }
    __syncthreads();

    for (int idx = t; idx < 1024; idx += 128) {
        int r = idx >> 4, c = (idx & 15) * 4;
        const float* xr = &sm.T[r * 65 + c];
        float4 v = make_float4(xr[0], xr[1], xr[2], xr[3]);
        *(float4*)(out + ((size_t)bz * SEQ + (p0 + r)) * SEQ + q0 + c) = v;
    }

    if (ti != tj) {
        for (int idx = t; idx < 1024; idx += 128) {
            int r = idx >> 4, c = (idx & 15) * 4;
            float4 v = make_float4(sm.T[(c + 0) * 65 + r],
                                   sm.T[(c + 1) * 65 + r],
                                   sm.T[(c + 2) * 65 + r],
                                   sm.T[(c + 3) * 65 + r]);
            *(float4*)(out + ((size_t)bz * SEQ + (q0 + r)) * SEQ + p0 + c) = v;
        }
    }
}

// ---------------------------------------------------------------------------
extern "C" void kernel_launch(void* const* d_in, const int* in_sizes, int n_in,
                              void* d_out, int out_size) {
    const float* query = (const float*)d_in[0];
    const float* attn  = (const float*)d_in[1];
    const float* pex   = (const float*)d_in[2];
    const float* pey   = (const float*)d_in[3];
    const float* wx    = (const float*)d_in[4];
    float* out = (float*)d_out;

    cope_kernel<<<2304, 512>>>(query, attn, pex, pey);

    dim3 dgrid(45, BATCH);
    dist_kernel<<<dgrid, 128>>>(wx, out);
}

// round 12
// speedup vs baseline: 1.3070x; 1.3070x over previous
#include <cuda_runtime.h>

#define NB      8
#define NHEADS  12
#define HH      24
#define SEQ     576
#define DIM     64
#define NPOS    24
#define BATCH   96
#define KPAD    28          // B row stride (words): 16B-aligned, tx*28 mod 32 distinct
#define ATPAD   68          // AT row stride (words): 272 B, 16B-aligned at every k

// Scratch: pe_x_flat / pe_y_flat  [BATCH][SEQ][NPOS]
__device__ __align__(16) float g_Vx[BATCH * SEQ * NPOS];
__device__ __align__(16) float g_Vy[BATCH * SEQ * NPOS];

__device__ __forceinline__ float sigmoidf_(float x) {
    return 1.0f / (1.0f + __expf(-x));
}

__device__ __forceinline__ unsigned long long fma2(unsigned long long a,
                                                   unsigned long long b,
                                                   unsigned long long c) {
    unsigned long long d;
    asm("fma.rn.f32x2 %0, %1, %2, %3;" : "=l"(d) : "l"(a), "l"(b), "l"(c));
    return d;
}

__device__ __forceinline__ unsigned long long pack2(float lo, float hi) {
    unsigned long long r;
    asm("mov.b64 %0, {%1, %2};" : "=l"(r) : "f"(lo), "f"(hi));
    return r;
}

__device__ __forceinline__ float fsqrt_approx(float x) {
    float r;
    asm("sqrt.approx.f32 %0, %1;" : "=f"(r) : "f"(x));
    return r;
}

// ---------------------------------------------------------------------------
// Kernel 1: fused CoPE (R6 form) with PATH-AGNOSTIC balanced GEMM:
// 576 (path, j, pp) tasks distributed over all 512 threads.
// ---------------------------------------------------------------------------
__global__ void __launch_bounds__(512) cope_kernel(
    const float* __restrict__ query,      // [8,12,576,64]
    const float* __restrict__ attn,       // [8,12,576,576]
    const float* __restrict__ pex,        // [64,24]
    const float* __restrict__ pey)        // [64,24]
{
    __shared__ __align__(16) float q_s[2][HH * 68];
    __shared__ __align__(16) float pe_s[2][DIM * NPOS];
    __shared__ __align__(8)  float li[2][HH * 26];

    int t    = threadIdx.x;
    int path = t >> 8;
    int tp   = t & 255;

    int id   = blockIdx.x;
    int n    = id / 12;
    int m    = id % 12;
    int b_a  = id / 288;
    int hd_a = (id / 24) % 12;
    int r_a  = id % 24;
    int b_q  = n / 24;
    int s_q  = n % 24;

    {
        const float4* pe4 = (const float4*)(path ? pey : pex);
        float4* d4 = (float4*)pe_s[path];
        for (int idx = tp; idx < DIM * NPOS / 4; idx += 256)
            d4[idx] = pe4[idx];
    }

    if (!path) {
        const float4* qb = (const float4*)(query + (((size_t)(b_q * 12 + m)) * SEQ + s_q * 24) * DIM);
        for (int idx = tp; idx < HH * DIM / 4; idx += 256) {
            int rr = idx >> 4, c4 = (idx & 15) * 4;
            *(float4*)&q_s[0][rr * 68 + c4] = qb[idx];
        }
    } else {
        const float* qb = query + (((size_t)(b_q * 12 + m)) * SEQ + s_q) * DIM;
        for (int idx = tp; idx < HH * DIM / 4; idx += 256) {
            int rr = idx >> 4, c4 = (idx & 15) * 4;
            *(float4*)&q_s[1][rr * 68 + c4] = *(const float4*)(qb + (size_t)rr * (24 * DIM) + c4);
        }
    }
    __syncthreads();

    // Balanced GEMM: 576 tasks (both paths) over 512 threads.
    for (int o = t; o < 2 * HH * 12; o += 512) {
        int pa  = (o >= 288) ? 1 : 0;
        int rem = o - pa * 288;
        int j   = rem / 12;
        int pp  = rem - j * 12;
        const float4* qr4 = (const float4*)&q_s[pa][j * 68];
        const float*  pr  = pe_s[pa] + 2 * pp;
        unsigned long long acc = 0ull;
        #pragma unroll
        for (int dq = 0; dq < 16; dq++) {
            float4 q4 = qr4[dq];
            float2 v0 = *(const float2*)(pr + (4 * dq + 0) * NPOS);
            float2 v1 = *(const float2*)(pr + (4 * dq + 1) * NPOS);
            float2 v2 = *(const float2*)(pr + (4 * dq + 2) * NPOS);
            float2 v3 = *(const float2*)(pr + (4 * dq + 3) * NPOS);
            acc = fma2(pack2(q4.x, q4.x), pack2(v0.x, v0.y), acc);
            acc = fma2(pack2(q4.y, q4.y), pack2(v1.x, v1.y), acc);
            acc = fma2(pack2(q4.z, q4.z), pack2(v2.x, v2.y), acc);
            acc = fma2(pack2(q4.w, q4.w), pack2(v3.x, v3.y), acc);
        }
        *(float2*)(&li[pa][j * 26 + 2 * pp]) = *(float2*)&acc;
    }
    __syncthreads();

    int w    = (t >> 5) & 7;
    int lane = t & 31;
    int bh   = b_q * 12 + m;
    for (int j = w; j < HH; j += 8) {
        const float* arow;
        int astride;
        float* dst;
        if (!path) {
            arow = attn + (((size_t)(b_a * 12 + hd_a)) * SEQ + (size_t)(r_a * 24 + j)) * SEQ
                        + (size_t)(r_a * 24);
            astride = 1;
            dst = g_Vx + ((size_t)bh * SEQ + (size_t)(s_q * 24 + j)) * NPOS;
        } else {
            arow = attn + (((size_t)(b_a * 12 + hd_a)) * SEQ + (size_t)(j * 24 + r_a)) * SEQ
                        + (size_t)r_a;
            astride = 24;
            dst = g_Vy + ((size_t)bh * SEQ + (size_t)(j * 24 + s_q)) * NPOS;
        }
        float v = 0.0f;
        if (lane < NPOS)
            v = sigmoidf_(arow[lane * astride]);
        #pragma unroll
        for (int d = 1; d < 32; d <<= 1) {
            float tv = __shfl_down_sync(0xffffffffu, v, d);
            if (lane + d < NPOS) v += tv;
        }
        if (lane < NPOS) {
            float pp = fminf(v, (float)(NPOS - 1));
            float pf = floorf(pp);
            int   ifl = (int)pf;
            int   ic  = (int)ceilf(pp);
            float wq  = pp - pf;
            float val = li[path][j * 26 + ic] * wq + li[path][j * 26 + ifl] * (1.0f - wq);
            dst[lane] = val;
        }
    }
}

// ---------------------------------------------------------------------------
// Kernel 2: fused double-cdist + mix. EXACT R8/R10 form — measured ~70 us.
// ---------------------------------------------------------------------------
union DistSm {
    struct { float AT[2][NPOS * ATPAD]; float B[2][64 * KPAD]; } m;
    float T[64 * 65];
};

__global__ void __launch_bounds__(128, 4) dist_kernel(
    const float* __restrict__ wxp,
    float* __restrict__ out)
{
    __shared__ __align__(16) DistSm sm;
    __shared__ float nA[2][64];
    __shared__ float nB[2][64];

    int bz = blockIdx.y;
    int u = blockIdx.x;
    int ti = 0;
    #pragma unroll 1
    while (u >= (9 - ti)) { u -= (9 - ti); ti++; }
    int tj = ti + u;
    int p0 = ti * 64;
    int q0 = tj * 64;

    int t  = threadIdx.x;     // 0..127
    int sg = t >> 6;          // s-path group
    int lt = t & 63;
    int tx = lt & 7;
    int ty = lt >> 3;

    #pragma unroll
    for (int s = 0; s < 2; s++) {
        const float* V = s ? g_Vy : g_Vx;
        const float4* ga = (const float4*)(V + ((size_t)bz * SEQ + p0) * NPOS);
        const float4* gb = (const float4*)(V + ((size_t)bz * SEQ + q0) * NPOS);
        for (int idx = t; idx < 64 * NPOS / 4; idx += 128) {   // 384 float4
            int r = idx / 6, c = (idx - r * 6) * 4;
            float4 va = ga[idx];
            sm.m.AT[s][(c + 0) * ATPAD + r] = va.x;
            sm.m.AT[s][(c + 1) * ATPAD + r] = va.y;
            sm.m.AT[s][(c + 2) * ATPAD + r] = va.z;
            sm.m.AT[s][(c + 3) * ATPAD + r] = va.w;
            *(float4*)&sm.m.B[s][r * KPAD + c] = gb[idx];
        }
    }
    __syncthreads();

    for (int o = t; o < 256; o += 128) {
        int s  = (o >> 7) & 1;
        int ab = (o >> 6) & 1;
        int r  = o & 63;
        float acc = 0.0f;
        if (ab) {
            const float* src = &sm.m.B[s][r * KPAD];
            #pragma unroll
            for (int k = 0; k < NPOS; k++)
                acc = fmaf(src[k], src[k], acc);
            nB[s][r] = acc;
        } else {
            const float* src = &sm.m.AT[s][r];
            #pragma unroll
            for (int k = 0; k < NPOS; k++) {
                float v = src[k * ATPAD];
                acc = fmaf(v, v, acc);
            }
            nA[s][r] = acc;
        }
    }
    __syncthreads();

    float wxv = *wxp;

    const float* ATs = sm.m.AT[sg];
    const float* Bs  = sm.m.B[sg];
    unsigned long long acc[2][2][8];   // [h][d][j]: rows 4ty+32h+2d(,+1), col tx+8j
    #pragma unroll
    for (int h = 0; h < 2; h++)
        #pragma unroll
        for (int d = 0; d < 2; d++)
            #pragma unroll
            for (int j = 0; j < 8; j++) acc[h][d][j] = 0ull;

    #pragma unroll
    for (int k2 = 0; k2 < NPOS / 2; k2++) {
        float2 bv[8];
        #pragma unroll
        for (int j = 0; j < 8; j++)
            bv[j] = *(const float2*)(Bs + (tx + 8 * j) * KPAD + 2 * k2);
        #pragma unroll
        for (int kk = 0; kk < 2; kk++) {
            int k = 2 * k2 + kk;
            unsigned long long a2[2][2];
            #pragma unroll
            for (int h = 0; h < 2; h++) {
                float4 av = *(const float4*)(ATs + k * ATPAD + 4 * ty + 32 * h);
                a2[h][0] = pack2(av.x, av.y);
                a2[h][1] = pack2(av.z, av.w);
            }
            #pragma unroll
            for (int j = 0; j < 8; j++) {
                float bk = kk ? bv[j].y : bv[j].x;
                unsigned long long b2 = pack2(bk, bk);
                #pragma unroll
                for (int h = 0; h < 2; h++) {
                    acc[h][0][j] = fma2(a2[h][0], b2, acc[h][0][j]);
                    acc[h][1][j] = fma2(a2[h][1], b2, acc[h][1][j]);
                }
            }
        }
    }
    __syncthreads();   // all reads of AT/B done before T overlays them

    if (sg == 1) {
        float scale = 1.0f - wxv;
        #pragma unroll
        for (int h = 0; h < 2; h++)
            #pragma unroll
            for (int d = 0; d < 2; d++) {
                int r = 4 * ty + 32 * h + 2 * d;
                float na0 = nA[1][r], na1 = nA[1][r + 1];
                #pragma unroll
                for (int j = 0; j < 8; j++) {
                    int c = tx + 8 * j;
                    float nb = nB[1][c];
                    float2 g = *(float2*)&acc[h][d][j];
                    float d20 = fmaxf(fmaf(-2.0f, g.x, na0 + nb), 0.0f);
                    float d21 = fmaxf(fmaf(-2.0f, g.y, na1 + nb), 0.0f);
                    sm.T[r * 65 + c]       = scale * fsqrt_approx(d20);
                    sm.T[(r + 1) * 65 + c] = scale * fsqrt_approx(d21);
                }
            }
    }
    __syncthreads();

    if (sg == 0) {
        float scale = wxv;
        #pragma unroll
        for (int h = 0; h < 2; h++)
            #pragma unroll
            for (int d = 0; d < 2; d++) {
                int r = 4 * ty + 32 * h + 2 * d;
                float na0 = nA[0][r], na1 = nA[0][r + 1];
                #pragma unroll
                for (int j = 0; j < 8; j++) {
                    int c = tx + 8 * j;
                    float nb = nB[0][c];
                    float2 g = *(float2*)&acc[h][d][j];
                    float d20 = fmaxf(fmaf(-2.0f, g.x, na0 + nb), 0.0f);
                    float d21 = fmaxf(fmaf(-2.0f, g.y, na1 + nb), 0.0f);
                    float f0 = fmaf(scale, fsqrt_approx(d20), sm.T[r * 65 + c]);
                    float f1 = fmaf(scale, fsqrt_approx(d21), sm.T[(r + 1) * 65 + c]);
                    if (p0 + r == q0 + c)     f0 = 0.0f;
                    if (p0 + r + 1 == q0 + c) f1 = 0.0f;
                    sm.T[r * 65 + c]       = f0;
                    sm.T[(r + 1) * 65 + c] = f1;
                }
            }
    }
    __syncthreads();

    for (int idx = t; idx < 1024; idx += 128) {
        int r = idx >> 4, c = (idx & 15) * 4;
        const float* xr = &sm.T[r * 65 + c];
        float4 v = make_float4(xr[0], xr[1], xr[2], xr[3]);
        *(float4*)(out + ((size_t)bz * SEQ + (p0 + r)) * SEQ + q0 + c) = v;
    }

    if (ti != tj) {
        for (int idx = t; idx < 1024; idx += 128) {
            int r = idx >> 4, c = (idx & 15) * 4;
            float4 v = make_float4(sm.T[(c + 0) * 65 + r],
                                   sm.T[(c + 1) * 65 + r],
                                   sm.T[(c + 2) * 65 + r],
                                   sm.T[(c + 3) * 65 + r]);
            *(float4*)(out + ((size_t)bz * SEQ + (q0 + r)) * SEQ + p0 + c) = v;
        }
    }
}

// ---------------------------------------------------------------------------
extern "C" void kernel_launch(void* const* d_in, const int* in_sizes, int n_in,
                              void* d_out, int out_size) {
    const float* query = (const float*)d_in[0];
    const float* attn  = (const float*)d_in[1];
    const float* pex   = (const float*)d_in[2];
    const float* pey   = (const float*)d_in[3];
    const float* wx    = (const float*)d_in[4];
    float* out = (float*)d_out;

    cope_kernel<<<2304, 512>>>(query, attn, pex, pey);

    dim3 dgrid(45, BATCH);
    dist_kernel<<<dgrid, 128>>>(wx, out);
}